// round 1
// baseline (speedup 1.0000x reference)
#include <cuda_runtime.h>
#include <math.h>

#define Bsz 2
#define Sdim 2048
#define Edim 1024
#define Hn 16
#define DHd 64
#define Adim 1024
#define Mrows (Bsz * Sdim)  // 4096

// Scratch (allocation-free rule: __device__ globals)
__device__ float g_Q[(size_t)Bsz * Hn * Sdim * DHd];  // [B,H,S,DH]
__device__ float g_K[(size_t)Bsz * Hn * Sdim * DHd];
__device__ float g_V[(size_t)Bsz * Hn * Sdim * DHd];
__device__ float g_O[(size_t)Bsz * Sdim * Adim];      // [B,S,A] concat-head layout

// ---------------------------------------------------------------------------
// Kernel 1: per-head QKV projection.
// grid = (Mrows/64, H, 3), block = 256. Computes a 64x64 tile of
// Y = x[Mrows,E] @ W_h[E,64] + b_h, written to [B,H,S,DH] layout.
// ---------------------------------------------------------------------------
__global__ __launch_bounds__(256) void proj_kernel(
    const float* __restrict__ x,
    const float* __restrict__ Wq, const float* __restrict__ bq,
    const float* __restrict__ Wk, const float* __restrict__ bk,
    const float* __restrict__ Wv, const float* __restrict__ bv)
{
    const int h = blockIdx.y;
    const int z = blockIdx.z;
    const float* W    = (z == 0 ? Wq : (z == 1 ? Wk : Wv)) + (size_t)h * Edim * DHd;
    const float* bias = (z == 0 ? bq : (z == 1 ? bk : bv)) + h * DHd;
    float* dst        = (z == 0 ? g_Q : (z == 1 ? g_K : g_V));

    __shared__ float As[16][64];  // [k][m]
    __shared__ float Bs[16][64];  // [k][n]

    const int tid = threadIdx.x;
    const int tx = tid & 15, ty = tid >> 4;
    const int m0 = blockIdx.x * 64;
    const int ar = tid >> 2, ac = (tid & 3) * 4;     // A load: row, col-group
    const int br = tid >> 4, bc = (tid & 15) * 4;    // B load: row, col-group

    float acc[4][4];
#pragma unroll
    for (int i = 0; i < 4; i++)
#pragma unroll
        for (int j = 0; j < 4; j++) acc[i][j] = 0.f;

    for (int k0 = 0; k0 < Edim; k0 += 16) {
        float4 av = *(const float4*)(x + (size_t)(m0 + ar) * Edim + k0 + ac);
        As[ac + 0][ar] = av.x;
        As[ac + 1][ar] = av.y;
        As[ac + 2][ar] = av.z;
        As[ac + 3][ar] = av.w;
        *(float4*)&Bs[br][bc] = *(const float4*)(W + (size_t)(k0 + br) * DHd + bc);
        __syncthreads();
#pragma unroll
        for (int k = 0; k < 16; k++) {
            float4 a = *(float4*)&As[k][ty * 4];
            float4 b = *(float4*)&Bs[k][tx * 4];
            acc[0][0] += a.x * b.x; acc[0][1] += a.x * b.y; acc[0][2] += a.x * b.z; acc[0][3] += a.x * b.w;
            acc[1][0] += a.y * b.x; acc[1][1] += a.y * b.y; acc[1][2] += a.y * b.z; acc[1][3] += a.y * b.w;
            acc[2][0] += a.z * b.x; acc[2][1] += a.z * b.y; acc[2][2] += a.z * b.z; acc[2][3] += a.z * b.w;
            acc[3][0] += a.w * b.x; acc[3][1] += a.w * b.y; acc[3][2] += a.w * b.z; acc[3][3] += a.w * b.w;
        }
        __syncthreads();
    }

#pragma unroll
    for (int i = 0; i < 4; i++) {
        int m = m0 + ty * 4 + i;
        int b = m >> 11;             // /Sdim
        int s = m & (Sdim - 1);
        float* op = dst + (((size_t)(b * Hn + h) * Sdim + s) * DHd) + tx * 4;
        float4 r;
        r.x = acc[i][0] + bias[tx * 4 + 0];
        r.y = acc[i][1] + bias[tx * 4 + 1];
        r.z = acc[i][2] + bias[tx * 4 + 2];
        r.w = acc[i][3] + bias[tx * 4 + 3];
        *(float4*)op = r;
    }
}

// ---------------------------------------------------------------------------
// Kernel 2: flash attention, fp32 SIMT.
// grid = (S/128, B*H), block = 128. Each thread owns one q row entirely in
// registers; K/V tiles (64x64) staged in smem; online softmax in 16-key chunks.
// ---------------------------------------------------------------------------
__global__ __launch_bounds__(128) void attn_kernel()
{
    const int bh = blockIdx.y;
    const int tid = threadIdx.x;
    const int r = blockIdx.x * 128 + tid;

    const float* Qp = g_Q + (size_t)bh * Sdim * DHd;
    const float* Kp = g_K + (size_t)bh * Sdim * DHd;
    const float* Vp = g_V + (size_t)bh * Sdim * DHd;

    float q[64], o[64];
#pragma unroll
    for (int i = 0; i < 16; i++) {
        float4 v = *(const float4*)(Qp + (size_t)r * DHd + i * 4);
        q[i * 4 + 0] = v.x; q[i * 4 + 1] = v.y; q[i * 4 + 2] = v.z; q[i * 4 + 3] = v.w;
    }
#pragma unroll
    for (int i = 0; i < 64; i++) o[i] = 0.f;
    float mrun = -INFINITY, lrun = 0.f;

    __shared__ float Ks[64][64];
    __shared__ float Vs[64][64];

    for (int t0 = 0; t0 < Sdim; t0 += 64) {
        __syncthreads();
#pragma unroll
        for (int i = 0; i < 8; i++) {
            int idx = tid + i * 128;               // float4 index, 0..1023
            int rr = idx >> 4, cc = (idx & 15) * 4;
            *(float4*)&Ks[rr][cc] = *(const float4*)(Kp + (size_t)(t0 + rr) * DHd + cc);
            *(float4*)&Vs[rr][cc] = *(const float4*)(Vp + (size_t)(t0 + rr) * DHd + cc);
        }
        __syncthreads();

#pragma unroll 1
        for (int c0 = 0; c0 < 64; c0 += 16) {
            float sv[16];
#pragma unroll
            for (int t = 0; t < 16; t++) {
                float acc = 0.f;
#pragma unroll
                for (int k = 0; k < 64; k += 4) {
                    float4 kv = *(float4*)&Ks[c0 + t][k];   // broadcast across warp
                    acc += q[k] * kv.x + q[k + 1] * kv.y + q[k + 2] * kv.z + q[k + 3] * kv.w;
                }
                sv[t] = acc * 0.125f;   // 1/sqrt(64)
            }
            float mx = mrun;
#pragma unroll
            for (int t = 0; t < 16; t++) mx = fmaxf(mx, sv[t]);
            float corr = __expf(mrun - mx);
            mrun = mx;
            lrun *= corr;
#pragma unroll
            for (int k = 0; k < 64; k++) o[k] *= corr;
#pragma unroll
            for (int t = 0; t < 16; t++) {
                sv[t] = __expf(sv[t] - mrun);
                lrun += sv[t];
            }
#pragma unroll
            for (int t = 0; t < 16; t++) {
                float p = sv[t];
#pragma unroll
                for (int k = 0; k < 64; k += 4) {
                    float4 vv = *(float4*)&Vs[c0 + t][k];   // broadcast across warp
                    o[k + 0] += p * vv.x; o[k + 1] += p * vv.y;
                    o[k + 2] += p * vv.z; o[k + 3] += p * vv.w;
                }
            }
        }
    }

    float inv = 1.0f / lrun;
    int b = bh >> 4, h = bh & 15;
    float* op = g_O + ((size_t)(b * Sdim + r)) * Adim + h * DHd;
#pragma unroll
    for (int k = 0; k < 64; k += 4) {
        float4 v;
        v.x = o[k + 0] * inv; v.y = o[k + 1] * inv;
        v.z = o[k + 2] * inv; v.w = o[k + 3] * inv;
        *(float4*)(op + k) = v;
    }
}

// ---------------------------------------------------------------------------
// Kernel 3: output projection. out[M,E] = g_O[M,A] @ Wo[A,E] + bo
// grid = (Mrows/64, E/64), block = 256. Same 64x64x16 tile as proj.
// ---------------------------------------------------------------------------
__global__ __launch_bounds__(256) void outproj_kernel(
    const float* __restrict__ Wo, const float* __restrict__ bo,
    float* __restrict__ out)
{
    __shared__ float As[16][64];
    __shared__ float Bs[16][64];

    const int tid = threadIdx.x;
    const int tx = tid & 15, ty = tid >> 4;
    const int m0 = blockIdx.x * 64, n0 = blockIdx.y * 64;
    const int ar = tid >> 2, ac = (tid & 3) * 4;
    const int br = tid >> 4, bc = (tid & 15) * 4;

    float acc[4][4];
#pragma unroll
    for (int i = 0; i < 4; i++)
#pragma unroll
        for (int j = 0; j < 4; j++) acc[i][j] = 0.f;

    for (int k0 = 0; k0 < Adim; k0 += 16) {
        float4 av = *(const float4*)(g_O + (size_t)(m0 + ar) * Adim + k0 + ac);
        As[ac + 0][ar] = av.x;
        As[ac + 1][ar] = av.y;
        As[ac + 2][ar] = av.z;
        As[ac + 3][ar] = av.w;
        *(float4*)&Bs[br][bc] = *(const float4*)(Wo + (size_t)(k0 + br) * Edim + n0 + bc);
        __syncthreads();
#pragma unroll
        for (int k = 0; k < 16; k++) {
            float4 a = *(float4*)&As[k][ty * 4];
            float4 b = *(float4*)&Bs[k][tx * 4];
            acc[0][0] += a.x * b.x; acc[0][1] += a.x * b.y; acc[0][2] += a.x * b.z; acc[0][3] += a.x * b.w;
            acc[1][0] += a.y * b.x; acc[1][1] += a.y * b.y; acc[1][2] += a.y * b.z; acc[1][3] += a.y * b.w;
            acc[2][0] += a.z * b.x; acc[2][1] += a.z * b.y; acc[2][2] += a.z * b.z; acc[2][3] += a.z * b.w;
            acc[3][0] += a.w * b.x; acc[3][1] += a.w * b.y; acc[3][2] += a.w * b.z; acc[3][3] += a.w * b.w;
        }
        __syncthreads();
    }

#pragma unroll
    for (int i = 0; i < 4; i++) {
        int m = m0 + ty * 4 + i;
        float* op = out + (size_t)m * Edim + n0 + tx * 4;
        float4 r;
        r.x = acc[i][0] + bo[n0 + tx * 4 + 0];
        r.y = acc[i][1] + bo[n0 + tx * 4 + 1];
        r.z = acc[i][2] + bo[n0 + tx * 4 + 2];
        r.w = acc[i][3] + bo[n0 + tx * 4 + 3];
        *(float4*)op = r;
    }
}

extern "C" void kernel_launch(void* const* d_in, const int* in_sizes, int n_in,
                              void* d_out, int out_size)
{
    const float* x  = (const float*)d_in[0];
    const float* Wq = (const float*)d_in[1];
    const float* bq = (const float*)d_in[2];
    const float* Wk = (const float*)d_in[3];
    const float* bk = (const float*)d_in[4];
    const float* Wv = (const float*)d_in[5];
    const float* bv = (const float*)d_in[6];
    const float* Wo = (const float*)d_in[7];
    const float* bo = (const float*)d_in[8];
    float* out = (float*)d_out;

    dim3 g1(Mrows / 64, Hn, 3);
    proj_kernel<<<g1, 256>>>(x, Wq, bq, Wk, bk, Wv, bv);

    dim3 g2(Sdim / 128, Bsz * Hn);
    attn_kernel<<<g2, 128>>>();

    dim3 g3(Mrows / 64, Edim / 64);
    outproj_kernel<<<g3, 256>>>(Wo, bo, out);
}

// round 3
// speedup vs baseline: 1.0341x; 1.0341x over previous
#include <cuda_runtime.h>
#include <math.h>

#define Bsz 2
#define Sdim 2048
#define Edim 1024
#define Hn 16
#define DHd 64
#define Adim 1024
#define Mrows (Bsz * Sdim)  // 4096

// Scratch (allocation-free rule: __device__ globals)
__device__ float g_Q[(size_t)Bsz * Hn * Sdim * DHd];  // [B,H,S,DH]
__device__ float g_K[(size_t)Bsz * Hn * Sdim * DHd];
__device__ float g_V[(size_t)Bsz * Hn * Sdim * DHd];
__device__ float g_O[(size_t)Bsz * Sdim * Adim];      // [B,S,A] concat-head layout

// ---------------------------------------------------------------------------
// Kernel 1: fused QKV projection as ONE logical GEMM (scalar FFMA)
//   C[4096, 3072] = x[4096,1024] @ Wcat[1024,3072] + bias
// column c -> z = c/1024 (q/k/v), h = (c/64)%16, d = c%64
// 128x128x8 tile, 256 threads, 8x8 microtile, double-buffered smem.
// ---------------------------------------------------------------------------
__global__ __launch_bounds__(256) void qkv_kernel(
    const float* __restrict__ x,
    const float* __restrict__ Wq, const float* __restrict__ bq,
    const float* __restrict__ Wk, const float* __restrict__ bk,
    const float* __restrict__ Wv, const float* __restrict__ bv)
{
    __shared__ float As[2][8][132];   // [buf][k][m], padded
    __shared__ float Bs[2][8][128];   // [buf][k][n]

    const int tid = threadIdx.x;
    const int m0 = blockIdx.x * 128;
    const int n0 = blockIdx.y * 128;          // whole 128-tile lies in one z
    const int z = n0 >> 10;
    const float* W    = (z == 0 ? Wq : (z == 1 ? Wk : Wv));
    const float* bias = (z == 0 ? bq : (z == 1 ? bk : bv));
    float* dst        = (z == 0 ? g_Q : (z == 1 ? g_K : g_V));

    // A loader: row = tid/2, kcol group = (tid&1)*4
    const int ar = tid >> 1;
    const int ac = (tid & 1) * 4;
    const float* Aptr = x + (size_t)(m0 + ar) * Edim + ac;
    // B loader: krow = tid/32, ncol group = (tid&31)*4
    const int kr = tid >> 5;
    const int nc = (tid & 31) * 4;
    const int cB = n0 + nc;                   // float4 never crosses a head (nc mult of 4)
    const float* Bptr = W + ((size_t)((cB >> 6) & 15)) * (Edim * DHd) + (cB & 63);

    const int tx = tid & 15, ty = tid >> 4;
    const int row0 = ty * 8, col0 = tx * 8;

    float acc[8][8];
#pragma unroll
    for (int i = 0; i < 8; i++)
#pragma unroll
        for (int j = 0; j < 8; j++) acc[i][j] = 0.f;

    // Preload tile 0 into buffer 0
    float4 aReg = *(const float4*)(Aptr);
    float4 bReg = *(const float4*)(Bptr + (size_t)kr * DHd);
    As[0][ac + 0][ar] = aReg.x;
    As[0][ac + 1][ar] = aReg.y;
    As[0][ac + 2][ar] = aReg.z;
    As[0][ac + 3][ar] = aReg.w;
    *(float4*)&Bs[0][kr][nc] = bReg;
    __syncthreads();

    int buf = 0;
    for (int k0 = 0; k0 < Edim; k0 += 8) {
        const bool more = (k0 + 8) < Edim;
        if (more) {
            aReg = *(const float4*)(Aptr + k0 + 8);
            bReg = *(const float4*)(Bptr + (size_t)(k0 + 8 + kr) * DHd);
        }
#pragma unroll
        for (int k = 0; k < 8; k++) {
            float a[8], b[8];
            float4 t0 = *(float4*)&As[buf][k][row0];
            float4 t1 = *(float4*)&As[buf][k][row0 + 4];
            a[0]=t0.x; a[1]=t0.y; a[2]=t0.z; a[3]=t0.w;
            a[4]=t1.x; a[5]=t1.y; a[6]=t1.z; a[7]=t1.w;
            float4 u0 = *(float4*)&Bs[buf][k][col0];
            float4 u1 = *(float4*)&Bs[buf][k][col0 + 4];
            b[0]=u0.x; b[1]=u0.y; b[2]=u0.z; b[3]=u0.w;
            b[4]=u1.x; b[5]=u1.y; b[6]=u1.z; b[7]=u1.w;
#pragma unroll
            for (int i = 0; i < 8; i++)
#pragma unroll
                for (int j = 0; j < 8; j++)
                    acc[i][j] += a[i] * b[j];
        }
        if (more) {
            int nb = buf ^ 1;
            As[nb][ac + 0][ar] = aReg.x;
            As[nb][ac + 1][ar] = aReg.y;
            As[nb][ac + 2][ar] = aReg.z;
            As[nb][ac + 3][ar] = aReg.w;
            *(float4*)&Bs[nb][kr][nc] = bReg;
        }
        __syncthreads();
        buf ^= 1;
    }

    // bias (index within z-array = c % 1024) and store to [B,H,S,DH]
    const int cb = n0 + col0;
    const float* bp = bias + (cb & 1023);
    float bv8[8];
#pragma unroll
    for (int j = 0; j < 8; j++) bv8[j] = bp[j];
    const int h = (cb >> 6) & 15;
    const int d = cb & 63;
#pragma unroll
    for (int i = 0; i < 8; i++) {
        int m = m0 + row0 + i;
        int b = m >> 11;
        int s = m & (Sdim - 1);
        float* op = dst + (((size_t)(b * Hn + h) * Sdim + s) * DHd) + d;
        float4 v0 = make_float4(acc[i][0] + bv8[0], acc[i][1] + bv8[1],
                                acc[i][2] + bv8[2], acc[i][3] + bv8[3]);
        float4 v1 = make_float4(acc[i][4] + bv8[4], acc[i][5] + bv8[5],
                                acc[i][6] + bv8[6], acc[i][7] + bv8[7]);
        *(float4*)op = v0;
        *(float4*)(op + 4) = v1;
    }
}

// ---------------------------------------------------------------------------
// Kernel 2: flash attention, fp32 SIMT (R1-proven body, verbatim).
// grid = (S/128, B*H), block = 128.
// ---------------------------------------------------------------------------
__global__ __launch_bounds__(128) void attn_kernel()
{
    const int bh = blockIdx.y;
    const int tid = threadIdx.x;
    const int r = blockIdx.x * 128 + tid;

    const float* Qp = g_Q + (size_t)bh * Sdim * DHd;
    const float* Kp = g_K + (size_t)bh * Sdim * DHd;
    const float* Vp = g_V + (size_t)bh * Sdim * DHd;

    float q[64], o[64];
#pragma unroll
    for (int i = 0; i < 16; i++) {
        float4 v = *(const float4*)(Qp + (size_t)r * DHd + i * 4);
        q[i * 4 + 0] = v.x; q[i * 4 + 1] = v.y; q[i * 4 + 2] = v.z; q[i * 4 + 3] = v.w;
    }
#pragma unroll
    for (int i = 0; i < 64; i++) o[i] = 0.f;
    float mrun = -INFINITY, lrun = 0.f;

    __shared__ float Ks[64][64];
    __shared__ float Vs[64][64];

    for (int t0 = 0; t0 < Sdim; t0 += 64) {
        __syncthreads();
#pragma unroll
        for (int i = 0; i < 8; i++) {
            int idx = tid + i * 128;               // float4 index, 0..1023
            int rr = idx >> 4, cc = (idx & 15) * 4;
            *(float4*)&Ks[rr][cc] = *(const float4*)(Kp + (size_t)(t0 + rr) * DHd + cc);
            *(float4*)&Vs[rr][cc] = *(const float4*)(Vp + (size_t)(t0 + rr) * DHd + cc);
        }
        __syncthreads();

#pragma unroll 1
        for (int c0 = 0; c0 < 64; c0 += 16) {
            float sv[16];
#pragma unroll
            for (int t = 0; t < 16; t++) {
                float acc = 0.f;
#pragma unroll
                for (int k = 0; k < 64; k += 4) {
                    float4 kv = *(float4*)&Ks[c0 + t][k];   // broadcast across warp
                    acc += q[k] * kv.x + q[k + 1] * kv.y + q[k + 2] * kv.z + q[k + 3] * kv.w;
                }
                sv[t] = acc * 0.125f;   // 1/sqrt(64)
            }
            float mx = mrun;
#pragma unroll
            for (int t = 0; t < 16; t++) mx = fmaxf(mx, sv[t]);
            float corr = __expf(mrun - mx);
            mrun = mx;
            lrun *= corr;
#pragma unroll
            for (int k = 0; k < 64; k++) o[k] *= corr;
#pragma unroll
            for (int t = 0; t < 16; t++) {
                sv[t] = __expf(sv[t] - mrun);
                lrun += sv[t];
            }
#pragma unroll
            for (int t = 0; t < 16; t++) {
                float p = sv[t];
#pragma unroll
                for (int k = 0; k < 64; k += 4) {
                    float4 vv = *(float4*)&Vs[c0 + t][k];   // broadcast across warp
                    o[k + 0] += p * vv.x; o[k + 1] += p * vv.y;
                    o[k + 2] += p * vv.z; o[k + 3] += p * vv.w;
                }
            }
        }
    }

    float inv = 1.0f / lrun;
    int b = bh >> 4, h = bh & 15;
    float* op = g_O + ((size_t)(b * Sdim + r)) * Adim + h * DHd;
#pragma unroll
    for (int k = 0; k < 64; k += 4) {
        float4 v;
        v.x = o[k + 0] * inv; v.y = o[k + 1] * inv;
        v.z = o[k + 2] * inv; v.w = o[k + 3] * inv;
        *(float4*)(op + k) = v;
    }
}

// ---------------------------------------------------------------------------
// Kernel 3: output projection (scalar FFMA, same 128x128x8 double-buffered tile)
// out[4096,1024] = g_O[4096,1024] @ Wo[1024,1024] + bo
// ---------------------------------------------------------------------------
__global__ __launch_bounds__(256) void outproj_kernel(
    const float* __restrict__ Wo, const float* __restrict__ bo,
    float* __restrict__ out)
{
    __shared__ float As[2][8][132];
    __shared__ float Bs[2][8][128];

    const int tid = threadIdx.x;
    const int m0 = blockIdx.x * 128;
    const int n0 = blockIdx.y * 128;

    const int ar = tid >> 1;
    const int ac = (tid & 1) * 4;
    const float* Aptr = g_O + (size_t)(m0 + ar) * Adim + ac;
    const int kr = tid >> 5;
    const int nc = (tid & 31) * 4;
    const float* Bptr = Wo + n0 + nc;

    const int tx = tid & 15, ty = tid >> 4;
    const int row0 = ty * 8, col0 = tx * 8;

    float acc[8][8];
#pragma unroll
    for (int i = 0; i < 8; i++)
#pragma unroll
        for (int j = 0; j < 8; j++) acc[i][j] = 0.f;

    float4 aReg = *(const float4*)(Aptr);
    float4 bReg = *(const float4*)(Bptr + (size_t)kr * Edim);
    As[0][ac + 0][ar] = aReg.x;
    As[0][ac + 1][ar] = aReg.y;
    As[0][ac + 2][ar] = aReg.z;
    As[0][ac + 3][ar] = aReg.w;
    *(float4*)&Bs[0][kr][nc] = bReg;
    __syncthreads();

    int buf = 0;
    for (int k0 = 0; k0 < Adim; k0 += 8) {
        const bool more = (k0 + 8) < Adim;
        if (more) {
            aReg = *(const float4*)(Aptr + k0 + 8);
            bReg = *(const float4*)(Bptr + (size_t)(k0 + 8 + kr) * Edim);
        }
#pragma unroll
        for (int k = 0; k < 8; k++) {
            float a[8], b[8];
            float4 t0 = *(float4*)&As[buf][k][row0];
            float4 t1 = *(float4*)&As[buf][k][row0 + 4];
            a[0]=t0.x; a[1]=t0.y; a[2]=t0.z; a[3]=t0.w;
            a[4]=t1.x; a[5]=t1.y; a[6]=t1.z; a[7]=t1.w;
            float4 u0 = *(float4*)&Bs[buf][k][col0];
            float4 u1 = *(float4*)&Bs[buf][k][col0 + 4];
            b[0]=u0.x; b[1]=u0.y; b[2]=u0.z; b[3]=u0.w;
            b[4]=u1.x; b[5]=u1.y; b[6]=u1.z; b[7]=u1.w;
#pragma unroll
            for (int i = 0; i < 8; i++)
#pragma unroll
                for (int j = 0; j < 8; j++)
                    acc[i][j] += a[i] * b[j];
        }
        if (more) {
            int nb = buf ^ 1;
            As[nb][ac + 0][ar] = aReg.x;
            As[nb][ac + 1][ar] = aReg.y;
            As[nb][ac + 2][ar] = aReg.z;
            As[nb][ac + 3][ar] = aReg.w;
            *(float4*)&Bs[nb][kr][nc] = bReg;
        }
        __syncthreads();
        buf ^= 1;
    }

    const float* bp = bo + n0 + col0;
#pragma unroll
    for (int i = 0; i < 8; i++) {
        int m = m0 + row0 + i;
        float* op = out + (size_t)m * Edim + n0 + col0;
        float4 v0 = make_float4(acc[i][0] + bp[0], acc[i][1] + bp[1],
                                acc[i][2] + bp[2], acc[i][3] + bp[3]);
        float4 v1 = make_float4(acc[i][4] + bp[4], acc[i][5] + bp[5],
                                acc[i][6] + bp[6], acc[i][7] + bp[7]);
        *(float4*)op = v0;
        *(float4*)(op + 4) = v1;
    }
}

extern "C" void kernel_launch(void* const* d_in, const int* in_sizes, int n_in,
                              void* d_out, int out_size)
{
    const float* x  = (const float*)d_in[0];
    const float* Wq = (const float*)d_in[1];
    const float* bq = (const float*)d_in[2];
    const float* Wk = (const float*)d_in[3];
    const float* bk = (const float*)d_in[4];
    const float* Wv = (const float*)d_in[5];
    const float* bv = (const float*)d_in[6];
    const float* Wo = (const float*)d_in[7];
    const float* bo = (const float*)d_in[8];
    float* out = (float*)d_out;

    dim3 g1(Mrows / 128, (3 * Hn * DHd) / 128);   // (32, 24)
    qkv_kernel<<<g1, 256>>>(x, Wq, bq, Wk, bk, Wv, bv);

    dim3 g2(Sdim / 128, Bsz * Hn);                // (16, 32)
    attn_kernel<<<g2, 128>>>();

    dim3 g3(Mrows / 128, Edim / 128);             // (32, 8)
    outproj_kernel<<<g3, 256>>>(Wo, bo, out);
}

// round 6
// speedup vs baseline: 1.3120x; 1.2688x over previous
#include <cuda_runtime.h>
#include <cuda_bf16.h>
#include <math.h>

#define Bsz 2
#define Sdim 2048
#define Edim 1024
#define Hn 16
#define DHd 64
#define Adim 1024
#define Mrows (Bsz * Sdim)  // 4096

// Scratch (allocation-free rule: __device__ globals)
__device__ float g_Q[(size_t)Bsz * Hn * Sdim * DHd];  // [B,H,S,DH]
__device__ float g_K[(size_t)Bsz * Hn * Sdim * DHd];
__device__ float g_V[(size_t)Bsz * Hn * Sdim * DHd];
__device__ float g_O[(size_t)Bsz * Sdim * Adim];      // [B,S,A] concat-head layout

// ---- mma.sync helpers --------------------------------------------------
__device__ __forceinline__ void ldsm_x4(unsigned* r, const void* p) {
    unsigned addr = (unsigned)__cvta_generic_to_shared(p);
    asm volatile("ldmatrix.sync.aligned.m8n8.x4.shared.b16 {%0,%1,%2,%3}, [%4];"
        : "=r"(r[0]), "=r"(r[1]), "=r"(r[2]), "=r"(r[3]) : "r"(addr));
}
__device__ __forceinline__ void ldsm_x4_t(unsigned* r, const void* p) {
    unsigned addr = (unsigned)__cvta_generic_to_shared(p);
    asm volatile("ldmatrix.sync.aligned.m8n8.x4.trans.shared.b16 {%0,%1,%2,%3}, [%4];"
        : "=r"(r[0]), "=r"(r[1]), "=r"(r[2]), "=r"(r[3]) : "r"(addr));
}
__device__ __forceinline__ void mma_bf16(float* c, const unsigned* a, const unsigned* b) {
    asm volatile("mma.sync.aligned.m16n8k16.row.col.f32.bf16.bf16.f32 "
        "{%0,%1,%2,%3}, {%4,%5,%6,%7}, {%8,%9}, {%0,%1,%2,%3};"
        : "+f"(c[0]), "+f"(c[1]), "+f"(c[2]), "+f"(c[3])
        : "r"(a[0]), "r"(a[1]), "r"(a[2]), "r"(a[3]), "r"(b[0]), "r"(b[1]));
}
// split fp32 -> bf16 hi + bf16 lo (residual)
__device__ __forceinline__ void cvt_hilo(float x, unsigned short& h, unsigned short& l) {
    __nv_bfloat16 bh = __float2bfloat16(x);
    float rem = x - __bfloat162float(bh);
    __nv_bfloat16 bl = __float2bfloat16(rem);
    h = __bfloat16_as_ushort(bh);
    l = __bfloat16_as_ushort(bl);
}
__device__ __forceinline__ unsigned pk(unsigned short a, unsigned short b) {
    return (unsigned)a | ((unsigned)b << 16);
}
__device__ __forceinline__ float ex2f(float x) {
    float y; asm("ex2.approx.ftz.f32 %0, %1;" : "=f"(y) : "f"(x)); return y;
}

// ---------------------------------------------------------------------------
// Kernel 1: fused QKV projection, bf16 hi/lo split on tensor cores.
//   C[4096,3072] = x @ Wcat + bias;  col c -> z=c/1024, h=(c/64)%16, d=c%64
// 128x128 block tile, 256 thr (8 warps: 2m x 4n), warp tile 64x32,
// k-step 16, double-buffered smem, 3 MMAs per tile (hi*hi + hi*lo + lo*hi).
// ---------------------------------------------------------------------------
__global__ __launch_bounds__(256) void qkv_kernel(
    const float* __restrict__ x,
    const float* __restrict__ Wq, const float* __restrict__ bq,
    const float* __restrict__ Wk, const float* __restrict__ bk,
    const float* __restrict__ Wv, const float* __restrict__ bv)
{
    __shared__ unsigned short As_h[2][128][24];  // [buf][m][k] pad 16->24 (48B row)
    __shared__ unsigned short As_l[2][128][24];
    __shared__ unsigned short Bs_h[2][16][136];  // [buf][k][n] pad 128->136 (272B row)
    __shared__ unsigned short Bs_l[2][16][136];

    const int tid = threadIdx.x;
    const int lane = tid & 31;
    const int warp = tid >> 5;
    const int wm = warp & 1;        // 2 m-warps of 64
    const int wn = warp >> 1;       // 4 n-warps of 32
    const int m0 = blockIdx.x * 128;
    const int n0 = blockIdx.y * 128;
    const int z = n0 >> 10;
    const float* W    = (z == 0 ? Wq : (z == 1 ? Wk : Wv));
    const float* bias = (z == 0 ? bq : (z == 1 ? bk : bv));
    float* dst        = (z == 0 ? g_Q : (z == 1 ? g_K : g_V));

    // A loader: row = tid/2 (0..127), k-part = (tid&1)*8
    const int arow = tid >> 1;
    const int apart = (tid & 1) * 8;
    const float* Ag = x + (size_t)(m0 + arow) * Edim + apart;
    // B loader: k = tid/16 (0..15), n-col group = (tid&15)*8 (within one head)
    const int bkr = tid >> 4;
    const int bj = (tid & 15) * 8;
    const int cB = n0 + bj;
    const float* Bg = W + (size_t)((cB >> 6) & 15) * (Edim * DHd) + (cB & 63);

    float C[4][4][4];
#pragma unroll
    for (int i = 0; i < 4; i++)
#pragma unroll
        for (int j = 0; j < 4; j++)
#pragma unroll
            for (int e = 0; e < 4; e++) C[i][j][e] = 0.f;

    float4 a0r, a1r, b0r, b1r;
    // preload k0 = 0
    a0r = *(const float4*)(Ag);
    a1r = *(const float4*)(Ag + 4);
    b0r = *(const float4*)(Bg + (size_t)bkr * DHd);
    b1r = *(const float4*)(Bg + (size_t)bkr * DHd + 4);
    {
        float av[8] = {a0r.x, a0r.y, a0r.z, a0r.w, a1r.x, a1r.y, a1r.z, a1r.w};
        float bw[8] = {b0r.x, b0r.y, b0r.z, b0r.w, b1r.x, b1r.y, b1r.z, b1r.w};
        unsigned short ah[8], al[8], bh[8], bl[8];
#pragma unroll
        for (int j = 0; j < 8; j++) { cvt_hilo(av[j], ah[j], al[j]); cvt_hilo(bw[j], bh[j], bl[j]); }
        *(uint4*)&As_h[0][arow][apart] = make_uint4(pk(ah[0],ah[1]), pk(ah[2],ah[3]), pk(ah[4],ah[5]), pk(ah[6],ah[7]));
        *(uint4*)&As_l[0][arow][apart] = make_uint4(pk(al[0],al[1]), pk(al[2],al[3]), pk(al[4],al[5]), pk(al[6],al[7]));
        *(uint4*)&Bs_h[0][bkr][bj]     = make_uint4(pk(bh[0],bh[1]), pk(bh[2],bh[3]), pk(bh[4],bh[5]), pk(bh[6],bh[7]));
        *(uint4*)&Bs_l[0][bkr][bj]     = make_uint4(pk(bl[0],bl[1]), pk(bl[2],bl[3]), pk(bl[4],bl[5]), pk(bl[6],bl[7]));
    }
    __syncthreads();

    const int lrow = lane & 15;          // ldmatrix row within tile
    const int lkoff = (lane >> 4) * 8;   // ldmatrix 8x8-half selector

    int buf = 0;
    for (int k0 = 0; k0 < Edim; k0 += 16) {
        const bool more = (k0 + 16) < Edim;
        if (more) {
            a0r = *(const float4*)(Ag + k0 + 16);
            a1r = *(const float4*)(Ag + k0 + 20);
            b0r = *(const float4*)(Bg + (size_t)(k0 + 16 + bkr) * DHd);
            b1r = *(const float4*)(Bg + (size_t)(k0 + 16 + bkr) * DHd + 4);
        }

        unsigned a_hi[4][4], a_lo[4][4], b_hi[4][2], b_lo[4][2];
#pragma unroll
        for (int mi = 0; mi < 4; mi++) {
            ldsm_x4(a_hi[mi], &As_h[buf][wm * 64 + mi * 16 + lrow][lkoff]);
            ldsm_x4(a_lo[mi], &As_l[buf][wm * 64 + mi * 16 + lrow][lkoff]);
        }
#pragma unroll
        for (int np = 0; np < 2; np++) {
            unsigned r[4];
            ldsm_x4_t(r, &Bs_h[buf][lrow][wn * 32 + np * 16 + lkoff]);
            b_hi[2*np][0] = r[0]; b_hi[2*np][1] = r[1];
            b_hi[2*np+1][0] = r[2]; b_hi[2*np+1][1] = r[3];
            ldsm_x4_t(r, &Bs_l[buf][lrow][wn * 32 + np * 16 + lkoff]);
            b_lo[2*np][0] = r[0]; b_lo[2*np][1] = r[1];
            b_lo[2*np+1][0] = r[2]; b_lo[2*np+1][1] = r[3];
        }
#pragma unroll
        for (int mi = 0; mi < 4; mi++)
#pragma unroll
            for (int ni = 0; ni < 4; ni++) {
                mma_bf16(C[mi][ni], a_hi[mi], b_hi[ni]);
                mma_bf16(C[mi][ni], a_hi[mi], b_lo[ni]);
                mma_bf16(C[mi][ni], a_lo[mi], b_hi[ni]);
            }

        if (more) {
            int nb = buf ^ 1;
            float av[8] = {a0r.x, a0r.y, a0r.z, a0r.w, a1r.x, a1r.y, a1r.z, a1r.w};
            float bw[8] = {b0r.x, b0r.y, b0r.z, b0r.w, b1r.x, b1r.y, b1r.z, b1r.w};
            unsigned short ah[8], al[8], bh[8], bl[8];
#pragma unroll
            for (int j = 0; j < 8; j++) { cvt_hilo(av[j], ah[j], al[j]); cvt_hilo(bw[j], bh[j], bl[j]); }
            *(uint4*)&As_h[nb][arow][apart] = make_uint4(pk(ah[0],ah[1]), pk(ah[2],ah[3]), pk(ah[4],ah[5]), pk(ah[6],ah[7]));
            *(uint4*)&As_l[nb][arow][apart] = make_uint4(pk(al[0],al[1]), pk(al[2],al[3]), pk(al[4],al[5]), pk(al[6],al[7]));
            *(uint4*)&Bs_h[nb][bkr][bj]     = make_uint4(pk(bh[0],bh[1]), pk(bh[2],bh[3]), pk(bh[4],bh[5]), pk(bh[6],bh[7]));
            *(uint4*)&Bs_l[nb][bkr][bj]     = make_uint4(pk(bl[0],bl[1]), pk(bl[2],bl[3]), pk(bl[4],bl[5]), pk(bl[6],bl[7]));
        }
        __syncthreads();
        buf ^= 1;
    }

    // epilogue: C frag rows (lane>>2, +8), cols (lane&3)*2 pairs
#pragma unroll
    for (int mi = 0; mi < 4; mi++)
#pragma unroll
        for (int ni = 0; ni < 4; ni++) {
            int gm = m0 + wm * 64 + mi * 16 + (lane >> 2);
            int gc = n0 + wn * 32 + ni * 8 + (lane & 3) * 2;
            float b0f = bias[gc & 1023];
            float b1f = bias[(gc & 1023) + 1];
            int h = (gc >> 6) & 15;
            int d = gc & 63;
            int bb = gm >> 11, s = gm & (Sdim - 1);
            float* p0 = dst + (((size_t)(bb * Hn + h) * Sdim + s) * DHd) + d;
            *(float2*)p0 = make_float2(C[mi][ni][0] + b0f, C[mi][ni][1] + b1f);
            int gm2 = gm + 8;
            int bb2 = gm2 >> 11, s2 = gm2 & (Sdim - 1);
            float* p1 = dst + (((size_t)(bb2 * Hn + h) * Sdim + s2) * DHd) + d;
            *(float2*)p1 = make_float2(C[mi][ni][2] + b0f, C[mi][ni][3] + b1f);
        }
}

// ---------------------------------------------------------------------------
// Kernel 2: flash attention, fp32 SIMT (R1-proven body; log2-domain exp via
// q prescale + conditional rescale — mathematically equivalent).
// grid = (S/128, B*H), block = 128.
// ---------------------------------------------------------------------------
__global__ __launch_bounds__(128) void attn_kernel()
{
    const int bh = blockIdx.y;
    const int tid = threadIdx.x;
    const int r = blockIdx.x * 128 + tid;

    const float* Qp = g_Q + (size_t)bh * Sdim * DHd;
    const float* Kp = g_K + (size_t)bh * Sdim * DHd;
    const float* Vp = g_V + (size_t)bh * Sdim * DHd;

    const float SCALE = 0.125f * 1.4426950408889634f;  // 1/sqrt(64) * log2(e)

    float q[64], o[64];
#pragma unroll
    for (int i = 0; i < 16; i++) {
        float4 v = *(const float4*)(Qp + (size_t)r * DHd + i * 4);
        q[i * 4 + 0] = v.x * SCALE; q[i * 4 + 1] = v.y * SCALE;
        q[i * 4 + 2] = v.z * SCALE; q[i * 4 + 3] = v.w * SCALE;
    }
#pragma unroll
    for (int i = 0; i < 64; i++) o[i] = 0.f;
    float mrun = -INFINITY, lrun = 0.f;

    __shared__ float Ks[64][64];
    __shared__ float Vs[64][64];

    for (int t0 = 0; t0 < Sdim; t0 += 64) {
        __syncthreads();
#pragma unroll
        for (int i = 0; i < 8; i++) {
            int idx = tid + i * 128;               // float4 index, 0..1023
            int rr = idx >> 4, cc = (idx & 15) * 4;
            *(float4*)&Ks[rr][cc] = *(const float4*)(Kp + (size_t)(t0 + rr) * DHd + cc);
            *(float4*)&Vs[rr][cc] = *(const float4*)(Vp + (size_t)(t0 + rr) * DHd + cc);
        }
        __syncthreads();

#pragma unroll 1
        for (int c0 = 0; c0 < 64; c0 += 16) {
            float sv[16];
#pragma unroll
            for (int t = 0; t < 16; t++) {
                float acc = 0.f;
#pragma unroll
                for (int k = 0; k < 64; k += 4) {
                    float4 kv = *(float4*)&Ks[c0 + t][k];   // broadcast across warp
                    acc += q[k] * kv.x + q[k + 1] * kv.y + q[k + 2] * kv.z + q[k + 3] * kv.w;
                }
                sv[t] = acc;                                // log2-domain score
            }
            float mx = mrun;
#pragma unroll
            for (int t = 0; t < 16; t++) mx = fmaxf(mx, sv[t]);
            if (mx > mrun) {
                float corr = ex2f(mrun - mx);
                mrun = mx;
                lrun *= corr;
#pragma unroll
                for (int k = 0; k < 64; k++) o[k] *= corr;
            }
#pragma unroll
            for (int t = 0; t < 16; t++) {
                sv[t] = ex2f(sv[t] - mrun);
                lrun += sv[t];
            }
#pragma unroll
            for (int t = 0; t < 16; t++) {
                float p = sv[t];
#pragma unroll
                for (int k = 0; k < 64; k += 4) {
                    float4 vv = *(float4*)&Vs[c0 + t][k];   // broadcast across warp
                    o[k + 0] += p * vv.x; o[k + 1] += p * vv.y;
                    o[k + 2] += p * vv.z; o[k + 3] += p * vv.w;
                }
            }
        }
    }

    float inv = 1.0f / lrun;
    int b = bh >> 4, h = bh & 15;
    float* op = g_O + ((size_t)(b * Sdim + r)) * Adim + h * DHd;
#pragma unroll
    for (int k = 0; k < 64; k += 4) {
        float4 v;
        v.x = o[k + 0] * inv; v.y = o[k + 1] * inv;
        v.z = o[k + 2] * inv; v.w = o[k + 3] * inv;
        *(float4*)(op + k) = v;
    }
}

// ---------------------------------------------------------------------------
// Kernel 3: output projection, same bf16 hi/lo MMA template.
// out[4096,1024] = g_O @ Wo + bo
// ---------------------------------------------------------------------------
__global__ __launch_bounds__(256) void outproj_kernel(
    const float* __restrict__ Wo, const float* __restrict__ bo,
    float* __restrict__ out)
{
    __shared__ unsigned short As_h[2][128][24];
    __shared__ unsigned short As_l[2][128][24];
    __shared__ unsigned short Bs_h[2][16][136];
    __shared__ unsigned short Bs_l[2][16][136];

    const int tid = threadIdx.x;
    const int lane = tid & 31;
    const int warp = tid >> 5;
    const int wm = warp & 1;
    const int wn = warp >> 1;
    const int m0 = blockIdx.x * 128;
    const int n0 = blockIdx.y * 128;

    const int arow = tid >> 1;
    const int apart = (tid & 1) * 8;
    const float* Ag = g_O + (size_t)(m0 + arow) * Adim + apart;
    const int bkr = tid >> 4;
    const int bj = (tid & 15) * 8;
    const float* Bg = Wo + n0 + bj;

    float C[4][4][4];
#pragma unroll
    for (int i = 0; i < 4; i++)
#pragma unroll
        for (int j = 0; j < 4; j++)
#pragma unroll
            for (int e = 0; e < 4; e++) C[i][j][e] = 0.f;

    float4 a0r, a1r, b0r, b1r;
    a0r = *(const float4*)(Ag);
    a1r = *(const float4*)(Ag + 4);
    b0r = *(const float4*)(Bg + (size_t)bkr * Edim);
    b1r = *(const float4*)(Bg + (size_t)bkr * Edim + 4);
    {
        float av[8] = {a0r.x, a0r.y, a0r.z, a0r.w, a1r.x, a1r.y, a1r.z, a1r.w};
        float bw[8] = {b0r.x, b0r.y, b0r.z, b0r.w, b1r.x, b1r.y, b1r.z, b1r.w};
        unsigned short ah[8], al[8], bh[8], bl[8];
#pragma unroll
        for (int j = 0; j < 8; j++) { cvt_hilo(av[j], ah[j], al[j]); cvt_hilo(bw[j], bh[j], bl[j]); }
        *(uint4*)&As_h[0][arow][apart] = make_uint4(pk(ah[0],ah[1]), pk(ah[2],ah[3]), pk(ah[4],ah[5]), pk(ah[6],ah[7]));
        *(uint4*)&As_l[0][arow][apart] = make_uint4(pk(al[0],al[1]), pk(al[2],al[3]), pk(al[4],al[5]), pk(al[6],al[7]));
        *(uint4*)&Bs_h[0][bkr][bj]     = make_uint4(pk(bh[0],bh[1]), pk(bh[2],bh[3]), pk(bh[4],bh[5]), pk(bh[6],bh[7]));
        *(uint4*)&Bs_l[0][bkr][bj]     = make_uint4(pk(bl[0],bl[1]), pk(bl[2],bl[3]), pk(bl[4],bl[5]), pk(bl[6],bl[7]));
    }
    __syncthreads();

    const int lrow = lane & 15;
    const int lkoff = (lane >> 4) * 8;

    int buf = 0;
    for (int k0 = 0; k0 < Adim; k0 += 16) {
        const bool more = (k0 + 16) < Adim;
        if (more) {
            a0r = *(const float4*)(Ag + k0 + 16);
            a1r = *(const float4*)(Ag + k0 + 20);
            b0r = *(const float4*)(Bg + (size_t)(k0 + 16 + bkr) * Edim);
            b1r = *(const float4*)(Bg + (size_t)(k0 + 16 + bkr) * Edim + 4);
        }

        unsigned a_hi[4][4], a_lo[4][4], b_hi[4][2], b_lo[4][2];
#pragma unroll
        for (int mi = 0; mi < 4; mi++) {
            ldsm_x4(a_hi[mi], &As_h[buf][wm * 64 + mi * 16 + lrow][lkoff]);
            ldsm_x4(a_lo[mi], &As_l[buf][wm * 64 + mi * 16 + lrow][lkoff]);
        }
#pragma unroll
        for (int np = 0; np < 2; np++) {
            unsigned r[4];
            ldsm_x4_t(r, &Bs_h[buf][lrow][wn * 32 + np * 16 + lkoff]);
            b_hi[2*np][0] = r[0]; b_hi[2*np][1] = r[1];
            b_hi[2*np+1][0] = r[2]; b_hi[2*np+1][1] = r[3];
            ldsm_x4_t(r, &Bs_l[buf][lrow][wn * 32 + np * 16 + lkoff]);
            b_lo[2*np][0] = r[0]; b_lo[2*np][1] = r[1];
            b_lo[2*np+1][0] = r[2]; b_lo[2*np+1][1] = r[3];
        }
#pragma unroll
        for (int mi = 0; mi < 4; mi++)
#pragma unroll
            for (int ni = 0; ni < 4; ni++) {
                mma_bf16(C[mi][ni], a_hi[mi], b_hi[ni]);
                mma_bf16(C[mi][ni], a_hi[mi], b_lo[ni]);
                mma_bf16(C[mi][ni], a_lo[mi], b_hi[ni]);
            }

        if (more) {
            int nb = buf ^ 1;
            float av[8] = {a0r.x, a0r.y, a0r.z, a0r.w, a1r.x, a1r.y, a1r.z, a1r.w};
            float bw[8] = {b0r.x, b0r.y, b0r.z, b0r.w, b1r.x, b1r.y, b1r.z, b1r.w};
            unsigned short ah[8], al[8], bh[8], bl[8];
#pragma unroll
            for (int j = 0; j < 8; j++) { cvt_hilo(av[j], ah[j], al[j]); cvt_hilo(bw[j], bh[j], bl[j]); }
            *(uint4*)&As_h[nb][arow][apart] = make_uint4(pk(ah[0],ah[1]), pk(ah[2],ah[3]), pk(ah[4],ah[5]), pk(ah[6],ah[7]));
            *(uint4*)&As_l[nb][arow][apart] = make_uint4(pk(al[0],al[1]), pk(al[2],al[3]), pk(al[4],al[5]), pk(al[6],al[7]));
            *(uint4*)&Bs_h[nb][bkr][bj]     = make_uint4(pk(bh[0],bh[1]), pk(bh[2],bh[3]), pk(bh[4],bh[5]), pk(bh[6],bh[7]));
            *(uint4*)&Bs_l[nb][bkr][bj]     = make_uint4(pk(bl[0],bl[1]), pk(bl[2],bl[3]), pk(bl[4],bl[5]), pk(bl[6],bl[7]));
        }
        __syncthreads();
        buf ^= 1;
    }

#pragma unroll
    for (int mi = 0; mi < 4; mi++)
#pragma unroll
        for (int ni = 0; ni < 4; ni++) {
            int gm = m0 + wm * 64 + mi * 16 + (lane >> 2);
            int gc = n0 + wn * 32 + ni * 8 + (lane & 3) * 2;
            float b0f = bo[gc], b1f = bo[gc + 1];
            float* p0 = out + (size_t)gm * Edim + gc;
            *(float2*)p0 = make_float2(C[mi][ni][0] + b0f, C[mi][ni][1] + b1f);
            float* p1 = out + (size_t)(gm + 8) * Edim + gc;
            *(float2*)p1 = make_float2(C[mi][ni][2] + b0f, C[mi][ni][3] + b1f);
        }
}

extern "C" void kernel_launch(void* const* d_in, const int* in_sizes, int n_in,
                              void* d_out, int out_size)
{
    const float* x  = (const float*)d_in[0];
    const float* Wq = (const float*)d_in[1];
    const float* bq = (const float*)d_in[2];
    const float* Wk = (const float*)d_in[3];
    const float* bk = (const float*)d_in[4];
    const float* Wv = (const float*)d_in[5];
    const float* bv = (const float*)d_in[6];
    const float* Wo = (const float*)d_in[7];
    const float* bo = (const float*)d_in[8];
    float* out = (float*)d_out;

    dim3 g1(Mrows / 128, (3 * Hn * DHd) / 128);   // (32, 24)
    qkv_kernel<<<g1, 256>>>(x, Wq, bq, Wk, bk, Wv, bv);

    dim3 g2(Sdim / 128, Bsz * Hn);                // (16, 32)
    attn_kernel<<<g2, 128>>>();

    dim3 g3(Mrows / 128, Edim / 128);             // (32, 8)
    outproj_kernel<<<g3, 256>>>(Wo, bo, out);
}

// round 7
// speedup vs baseline: 3.0565x; 2.3297x over previous
#include <cuda_runtime.h>
#include <cuda_bf16.h>
#include <math.h>

#define Bsz 2
#define Sdim 2048
#define Edim 1024
#define Hn 16
#define DHd 64
#define Adim 1024
#define Mrows (Bsz * Sdim)  // 4096

// Scratch (allocation-free rule: __device__ globals)
__device__ float g_Q[(size_t)Bsz * Hn * Sdim * DHd];  // [B,H,S,DH]
__device__ float g_K[(size_t)Bsz * Hn * Sdim * DHd];
__device__ float g_V[(size_t)Bsz * Hn * Sdim * DHd];
__device__ float g_O[(size_t)Bsz * Sdim * Adim];      // [B,S,A] concat-head layout

// ---- mma.sync helpers --------------------------------------------------
__device__ __forceinline__ void ldsm_x4(unsigned* r, const void* p) {
    unsigned addr = (unsigned)__cvta_generic_to_shared(p);
    asm volatile("ldmatrix.sync.aligned.m8n8.x4.shared.b16 {%0,%1,%2,%3}, [%4];"
        : "=r"(r[0]), "=r"(r[1]), "=r"(r[2]), "=r"(r[3]) : "r"(addr));
}
__device__ __forceinline__ void ldsm_x4_t(unsigned* r, const void* p) {
    unsigned addr = (unsigned)__cvta_generic_to_shared(p);
    asm volatile("ldmatrix.sync.aligned.m8n8.x4.trans.shared.b16 {%0,%1,%2,%3}, [%4];"
        : "=r"(r[0]), "=r"(r[1]), "=r"(r[2]), "=r"(r[3]) : "r"(addr));
}
__device__ __forceinline__ void mma_bf16(float* c, const unsigned* a, const unsigned* b) {
    asm volatile("mma.sync.aligned.m16n8k16.row.col.f32.bf16.bf16.f32 "
        "{%0,%1,%2,%3}, {%4,%5,%6,%7}, {%8,%9}, {%0,%1,%2,%3};"
        : "+f"(c[0]), "+f"(c[1]), "+f"(c[2]), "+f"(c[3])
        : "r"(a[0]), "r"(a[1]), "r"(a[2]), "r"(a[3]), "r"(b[0]), "r"(b[1]));
}
// split fp32 -> bf16 hi + bf16 lo (residual)
__device__ __forceinline__ void cvt_hilo(float x, unsigned short& h, unsigned short& l) {
    __nv_bfloat16 bh = __float2bfloat16(x);
    float rem = x - __bfloat162float(bh);
    __nv_bfloat16 bl = __float2bfloat16(rem);
    h = __bfloat16_as_ushort(bh);
    l = __bfloat16_as_ushort(bl);
}
__device__ __forceinline__ unsigned pk(unsigned short a, unsigned short b) {
    return (unsigned)a | ((unsigned)b << 16);
}
// pack two floats into hi-pair and lo-pair bf16x2
__device__ __forceinline__ void hilo_pair(float x, float y, unsigned& h, unsigned& l) {
    unsigned short hx, lx, hy, ly;
    cvt_hilo(x, hx, lx);
    cvt_hilo(y, hy, ly);
    h = pk(hx, hy);
    l = pk(lx, ly);
}
__device__ __forceinline__ float ex2f(float x) {
    float y; asm("ex2.approx.ftz.f32 %0, %1;" : "=f"(y) : "f"(x)); return y;
}

// ---------------------------------------------------------------------------
// Kernel 1: fused QKV projection, bf16 hi/lo split on tensor cores (R6-proven).
// ---------------------------------------------------------------------------
__global__ __launch_bounds__(256) void qkv_kernel(
    const float* __restrict__ x,
    const float* __restrict__ Wq, const float* __restrict__ bq,
    const float* __restrict__ Wk, const float* __restrict__ bk,
    const float* __restrict__ Wv, const float* __restrict__ bv)
{
    __shared__ unsigned short As_h[2][128][24];  // [buf][m][k] pad 16->24 (48B row)
    __shared__ unsigned short As_l[2][128][24];
    __shared__ unsigned short Bs_h[2][16][136];  // [buf][k][n] pad 128->136 (272B row)
    __shared__ unsigned short Bs_l[2][16][136];

    const int tid = threadIdx.x;
    const int lane = tid & 31;
    const int warp = tid >> 5;
    const int wm = warp & 1;        // 2 m-warps of 64
    const int wn = warp >> 1;       // 4 n-warps of 32
    const int m0 = blockIdx.x * 128;
    const int n0 = blockIdx.y * 128;
    const int z = n0 >> 10;
    const float* W    = (z == 0 ? Wq : (z == 1 ? Wk : Wv));
    const float* bias = (z == 0 ? bq : (z == 1 ? bk : bv));
    float* dst        = (z == 0 ? g_Q : (z == 1 ? g_K : g_V));

    const int arow = tid >> 1;
    const int apart = (tid & 1) * 8;
    const float* Ag = x + (size_t)(m0 + arow) * Edim + apart;
    const int bkr = tid >> 4;
    const int bj = (tid & 15) * 8;
    const int cB = n0 + bj;
    const float* Bg = W + (size_t)((cB >> 6) & 15) * (Edim * DHd) + (cB & 63);

    float C[4][4][4];
#pragma unroll
    for (int i = 0; i < 4; i++)
#pragma unroll
        for (int j = 0; j < 4; j++)
#pragma unroll
            for (int e = 0; e < 4; e++) C[i][j][e] = 0.f;

    float4 a0r, a1r, b0r, b1r;
    a0r = *(const float4*)(Ag);
    a1r = *(const float4*)(Ag + 4);
    b0r = *(const float4*)(Bg + (size_t)bkr * DHd);
    b1r = *(const float4*)(Bg + (size_t)bkr * DHd + 4);
    {
        float av[8] = {a0r.x, a0r.y, a0r.z, a0r.w, a1r.x, a1r.y, a1r.z, a1r.w};
        float bw[8] = {b0r.x, b0r.y, b0r.z, b0r.w, b1r.x, b1r.y, b1r.z, b1r.w};
        unsigned short ah[8], al[8], bh[8], bl[8];
#pragma unroll
        for (int j = 0; j < 8; j++) { cvt_hilo(av[j], ah[j], al[j]); cvt_hilo(bw[j], bh[j], bl[j]); }
        *(uint4*)&As_h[0][arow][apart] = make_uint4(pk(ah[0],ah[1]), pk(ah[2],ah[3]), pk(ah[4],ah[5]), pk(ah[6],ah[7]));
        *(uint4*)&As_l[0][arow][apart] = make_uint4(pk(al[0],al[1]), pk(al[2],al[3]), pk(al[4],al[5]), pk(al[6],al[7]));
        *(uint4*)&Bs_h[0][bkr][bj]     = make_uint4(pk(bh[0],bh[1]), pk(bh[2],bh[3]), pk(bh[4],bh[5]), pk(bh[6],bh[7]));
        *(uint4*)&Bs_l[0][bkr][bj]     = make_uint4(pk(bl[0],bl[1]), pk(bl[2],bl[3]), pk(bl[4],bl[5]), pk(bl[6],bl[7]));
    }
    __syncthreads();

    const int lrow = lane & 15;
    const int lkoff = (lane >> 4) * 8;

    int buf = 0;
    for (int k0 = 0; k0 < Edim; k0 += 16) {
        const bool more = (k0 + 16) < Edim;
        if (more) {
            a0r = *(const float4*)(Ag + k0 + 16);
            a1r = *(const float4*)(Ag + k0 + 20);
            b0r = *(const float4*)(Bg + (size_t)(k0 + 16 + bkr) * DHd);
            b1r = *(const float4*)(Bg + (size_t)(k0 + 16 + bkr) * DHd + 4);
        }

        unsigned a_hi[4][4], a_lo[4][4], b_hi[4][2], b_lo[4][2];
#pragma unroll
        for (int mi = 0; mi < 4; mi++) {
            ldsm_x4(a_hi[mi], &As_h[buf][wm * 64 + mi * 16 + lrow][lkoff]);
            ldsm_x4(a_lo[mi], &As_l[buf][wm * 64 + mi * 16 + lrow][lkoff]);
        }
#pragma unroll
        for (int np = 0; np < 2; np++) {
            unsigned r[4];
            ldsm_x4_t(r, &Bs_h[buf][lrow][wn * 32 + np * 16 + lkoff]);
            b_hi[2*np][0] = r[0]; b_hi[2*np][1] = r[1];
            b_hi[2*np+1][0] = r[2]; b_hi[2*np+1][1] = r[3];
            ldsm_x4_t(r, &Bs_l[buf][lrow][wn * 32 + np * 16 + lkoff]);
            b_lo[2*np][0] = r[0]; b_lo[2*np][1] = r[1];
            b_lo[2*np+1][0] = r[2]; b_lo[2*np+1][1] = r[3];
        }
#pragma unroll
        for (int mi = 0; mi < 4; mi++)
#pragma unroll
            for (int ni = 0; ni < 4; ni++) {
                mma_bf16(C[mi][ni], a_hi[mi], b_hi[ni]);
                mma_bf16(C[mi][ni], a_hi[mi], b_lo[ni]);
                mma_bf16(C[mi][ni], a_lo[mi], b_hi[ni]);
            }

        if (more) {
            int nb = buf ^ 1;
            float av[8] = {a0r.x, a0r.y, a0r.z, a0r.w, a1r.x, a1r.y, a1r.z, a1r.w};
            float bw[8] = {b0r.x, b0r.y, b0r.z, b0r.w, b1r.x, b1r.y, b1r.z, b1r.w};
            unsigned short ah[8], al[8], bh[8], bl[8];
#pragma unroll
            for (int j = 0; j < 8; j++) { cvt_hilo(av[j], ah[j], al[j]); cvt_hilo(bw[j], bh[j], bl[j]); }
            *(uint4*)&As_h[nb][arow][apart] = make_uint4(pk(ah[0],ah[1]), pk(ah[2],ah[3]), pk(ah[4],ah[5]), pk(ah[6],ah[7]));
            *(uint4*)&As_l[nb][arow][apart] = make_uint4(pk(al[0],al[1]), pk(al[2],al[3]), pk(al[4],al[5]), pk(al[6],al[7]));
            *(uint4*)&Bs_h[nb][bkr][bj]     = make_uint4(pk(bh[0],bh[1]), pk(bh[2],bh[3]), pk(bh[4],bh[5]), pk(bh[6],bh[7]));
            *(uint4*)&Bs_l[nb][bkr][bj]     = make_uint4(pk(bl[0],bl[1]), pk(bl[2],bl[3]), pk(bl[4],bl[5]), pk(bl[6],bl[7]));
        }
        __syncthreads();
        buf ^= 1;
    }

#pragma unroll
    for (int mi = 0; mi < 4; mi++)
#pragma unroll
        for (int ni = 0; ni < 4; ni++) {
            int gm = m0 + wm * 64 + mi * 16 + (lane >> 2);
            int gc = n0 + wn * 32 + ni * 8 + (lane & 3) * 2;
            float b0f = bias[gc & 1023];
            float b1f = bias[(gc & 1023) + 1];
            int h = (gc >> 6) & 15;
            int d = gc & 63;
            int bb = gm >> 11, s = gm & (Sdim - 1);
            float* p0 = dst + (((size_t)(bb * Hn + h) * Sdim + s) * DHd) + d;
            *(float2*)p0 = make_float2(C[mi][ni][0] + b0f, C[mi][ni][1] + b1f);
            int gm2 = gm + 8;
            int bb2 = gm2 >> 11, s2 = gm2 & (Sdim - 1);
            float* p1 = dst + (((size_t)(bb2 * Hn + h) * Sdim + s2) * DHd) + d;
            *(float2*)p1 = make_float2(C[mi][ni][2] + b0f, C[mi][ni][3] + b1f);
        }
}

// ---------------------------------------------------------------------------
// Kernel 2: flash attention on tensor cores (bf16 hi/lo, m16n8k16).
// grid = (S/128, B*H), block = 256 (8 warps x 16 q-rows).
// K/V tiles (64 keys) staged hi/lo in smem; Q as register A-fragments;
// online softmax in accumulator layout; P repacked in-register for P@V.
// ---------------------------------------------------------------------------
__global__ __launch_bounds__(256) void attn_kernel()
{
    __shared__ unsigned short Ks_h[64][72];  // [key][dh] pad 64->72 (144B rows)
    __shared__ unsigned short Ks_l[64][72];
    __shared__ unsigned short Vs_h[64][72];
    __shared__ unsigned short Vs_l[64][72];

    const int bh = blockIdx.y;
    const int tid = threadIdx.x;
    const int lane = tid & 31;
    const int warp = tid >> 5;

    const float* Qp = g_Q + (size_t)bh * Sdim * DHd;
    const float* Kp = g_K + (size_t)bh * Sdim * DHd;
    const float* Vp = g_V + (size_t)bh * Sdim * DHd;

    const float SCALE = 0.125f * 1.4426950408889634f;  // 1/sqrt(64) * log2(e)

    // Q A-fragments, hi/lo, 4 k-steps of 16
    unsigned aq_h[4][4], aq_l[4][4];
    {
        const int r0 = blockIdx.x * 128 + warp * 16 + (lane >> 2);
        const int r1 = r0 + 8;
        const int cb = (lane & 3) * 2;
#pragma unroll
        for (int kk = 0; kk < 4; kk++) {
            float2 v00 = *(const float2*)(Qp + (size_t)r0 * DHd + kk * 16 + cb);
            float2 v01 = *(const float2*)(Qp + (size_t)r0 * DHd + kk * 16 + cb + 8);
            float2 v10 = *(const float2*)(Qp + (size_t)r1 * DHd + kk * 16 + cb);
            float2 v11 = *(const float2*)(Qp + (size_t)r1 * DHd + kk * 16 + cb + 8);
            hilo_pair(v00.x * SCALE, v00.y * SCALE, aq_h[kk][0], aq_l[kk][0]);
            hilo_pair(v10.x * SCALE, v10.y * SCALE, aq_h[kk][1], aq_l[kk][1]);
            hilo_pair(v01.x * SCALE, v01.y * SCALE, aq_h[kk][2], aq_l[kk][2]);
            hilo_pair(v11.x * SCALE, v11.y * SCALE, aq_h[kk][3], aq_l[kk][3]);
        }
    }

    float o[8][4];
#pragma unroll
    for (int i = 0; i < 8; i++)
#pragma unroll
        for (int e = 0; e < 4; e++) o[i][e] = 0.f;
    float m0_ = -INFINITY, m1_ = -INFINITY, l0_ = 0.f, l1_ = 0.f;

    const int l15 = lane & 15;
    const int lk8 = (lane >> 4) * 8;

    for (int t0 = 0; t0 < Sdim; t0 += 64) {
        __syncthreads();
        // Stage K/V tile as hi/lo bf16
#pragma unroll
        for (int i = 0; i < 4; i++) {
            int idx = tid + i * 256;            // 0..1023 float4s
            int row = idx >> 4, c4 = (idx & 15) * 4;
            float4 kv = *(const float4*)(Kp + (size_t)(t0 + row) * DHd + c4);
            float4 vv = *(const float4*)(Vp + (size_t)(t0 + row) * DHd + c4);
            unsigned h0, l0, h1, l1;
            hilo_pair(kv.x, kv.y, h0, l0); hilo_pair(kv.z, kv.w, h1, l1);
            *(uint2*)&Ks_h[row][c4] = make_uint2(h0, h1);
            *(uint2*)&Ks_l[row][c4] = make_uint2(l0, l1);
            hilo_pair(vv.x, vv.y, h0, l0); hilo_pair(vv.z, vv.w, h1, l1);
            *(uint2*)&Vs_h[row][c4] = make_uint2(h0, h1);
            *(uint2*)&Vs_l[row][c4] = make_uint2(l0, l1);
        }
        __syncthreads();

        // --- scores S = Q @ K^T  (m16 x n64), hi/lo 3-term ---
        float sc[8][4];
#pragma unroll
        for (int i = 0; i < 8; i++)
#pragma unroll
            for (int e = 0; e < 4; e++) sc[i][e] = 0.f;

#pragma unroll
        for (int kk = 0; kk < 4; kk++) {
#pragma unroll
            for (int pp = 0; pp < 4; pp++) {
                unsigned rh[4], rl[4];
                ldsm_x4(rh, &Ks_h[pp * 16 + l15][kk * 16 + lk8]);
                ldsm_x4(rl, &Ks_l[pp * 16 + l15][kk * 16 + lk8]);
                unsigned bh0[2] = {rh[0], rh[2]}, bh1[2] = {rh[1], rh[3]};
                unsigned bl0[2] = {rl[0], rl[2]}, bl1[2] = {rl[1], rl[3]};
                mma_bf16(sc[2*pp],   aq_h[kk], bh0);
                mma_bf16(sc[2*pp],   aq_h[kk], bl0);
                mma_bf16(sc[2*pp],   aq_l[kk], bh0);
                mma_bf16(sc[2*pp+1], aq_h[kk], bh1);
                mma_bf16(sc[2*pp+1], aq_h[kk], bl1);
                mma_bf16(sc[2*pp+1], aq_l[kk], bh1);
            }
        }

        // --- online softmax (log2 domain) ---
        float mx0 = m0_, mx1 = m1_;
#pragma unroll
        for (int i = 0; i < 8; i++) {
            mx0 = fmaxf(mx0, fmaxf(sc[i][0], sc[i][1]));
            mx1 = fmaxf(mx1, fmaxf(sc[i][2], sc[i][3]));
        }
        mx0 = fmaxf(mx0, __shfl_xor_sync(0xffffffffu, mx0, 1));
        mx0 = fmaxf(mx0, __shfl_xor_sync(0xffffffffu, mx0, 2));
        mx1 = fmaxf(mx1, __shfl_xor_sync(0xffffffffu, mx1, 1));
        mx1 = fmaxf(mx1, __shfl_xor_sync(0xffffffffu, mx1, 2));
        if (mx0 > m0_) {
            float corr = ex2f(m0_ - mx0);
            m0_ = mx0; l0_ *= corr;
#pragma unroll
            for (int i = 0; i < 8; i++) { o[i][0] *= corr; o[i][1] *= corr; }
        }
        if (mx1 > m1_) {
            float corr = ex2f(m1_ - mx1);
            m1_ = mx1; l1_ *= corr;
#pragma unroll
            for (int i = 0; i < 8; i++) { o[i][2] *= corr; o[i][3] *= corr; }
        }
        float ts0 = 0.f, ts1 = 0.f;
#pragma unroll
        for (int i = 0; i < 8; i++) {
            sc[i][0] = ex2f(sc[i][0] - m0_);
            sc[i][1] = ex2f(sc[i][1] - m0_);
            sc[i][2] = ex2f(sc[i][2] - m1_);
            sc[i][3] = ex2f(sc[i][3] - m1_);
            ts0 += sc[i][0] + sc[i][1];
            ts1 += sc[i][2] + sc[i][3];
        }
        ts0 += __shfl_xor_sync(0xffffffffu, ts0, 1);
        ts0 += __shfl_xor_sync(0xffffffffu, ts0, 2);
        ts1 += __shfl_xor_sync(0xffffffffu, ts1, 1);
        ts1 += __shfl_xor_sync(0xffffffffu, ts1, 2);
        l0_ += ts0; l1_ += ts1;

        // --- O += P @ V  (m16 k64 x n64), hi/lo 3-term ---
#pragma unroll
        for (int ss = 0; ss < 4; ss++) {
            unsigned ap_h[4], ap_l[4];
            hilo_pair(sc[2*ss][0],   sc[2*ss][1],   ap_h[0], ap_l[0]);
            hilo_pair(sc[2*ss][2],   sc[2*ss][3],   ap_h[1], ap_l[1]);
            hilo_pair(sc[2*ss+1][0], sc[2*ss+1][1], ap_h[2], ap_l[2]);
            hilo_pair(sc[2*ss+1][2], sc[2*ss+1][3], ap_h[3], ap_l[3]);
#pragma unroll
            for (int np = 0; np < 4; np++) {
                unsigned vh[4], vl[4];
                ldsm_x4_t(vh, &Vs_h[ss * 16 + l15][np * 16 + lk8]);
                ldsm_x4_t(vl, &Vs_l[ss * 16 + l15][np * 16 + lk8]);
                unsigned bh0[2] = {vh[0], vh[1]}, bh1[2] = {vh[2], vh[3]};
                unsigned bl0[2] = {vl[0], vl[1]}, bl1[2] = {vl[2], vl[3]};
                mma_bf16(o[2*np],   ap_h, bh0);
                mma_bf16(o[2*np],   ap_h, bl0);
                mma_bf16(o[2*np],   ap_l, bh0);
                mma_bf16(o[2*np+1], ap_h, bh1);
                mma_bf16(o[2*np+1], ap_h, bl1);
                mma_bf16(o[2*np+1], ap_l, bh1);
            }
        }
    }

    // --- write normalized O to concat-head layout ---
    const float inv0 = 1.0f / l0_, inv1 = 1.0f / l1_;
    const int b = bh >> 4, h = bh & 15;
    const int r0 = blockIdx.x * 128 + warp * 16 + (lane >> 2);
    float* op0 = g_O + (size_t)(b * Sdim + r0) * Adim + h * DHd;
    float* op1 = g_O + (size_t)(b * Sdim + r0 + 8) * Adim + h * DHd;
#pragma unroll
    for (int np = 0; np < 8; np++) {
        int col = np * 8 + (lane & 3) * 2;
        *(float2*)(op0 + col) = make_float2(o[np][0] * inv0, o[np][1] * inv0);
        *(float2*)(op1 + col) = make_float2(o[np][2] * inv1, o[np][3] * inv1);
    }
}

// ---------------------------------------------------------------------------
// Kernel 3: output projection, bf16 hi/lo MMA (R6-proven).
// ---------------------------------------------------------------------------
__global__ __launch_bounds__(256) void outproj_kernel(
    const float* __restrict__ Wo, const float* __restrict__ bo,
    float* __restrict__ out)
{
    __shared__ unsigned short As_h[2][128][24];
    __shared__ unsigned short As_l[2][128][24];
    __shared__ unsigned short Bs_h[2][16][136];
    __shared__ unsigned short Bs_l[2][16][136];

    const int tid = threadIdx.x;
    const int lane = tid & 31;
    const int warp = tid >> 5;
    const int wm = warp & 1;
    const int wn = warp >> 1;
    const int m0 = blockIdx.x * 128;
    const int n0 = blockIdx.y * 128;

    const int arow = tid >> 1;
    const int apart = (tid & 1) * 8;
    const float* Ag = g_O + (size_t)(m0 + arow) * Adim + apart;
    const int bkr = tid >> 4;
    const int bj = (tid & 15) * 8;
    const float* Bg = Wo + n0 + bj;

    float C[4][4][4];
#pragma unroll
    for (int i = 0; i < 4; i++)
#pragma unroll
        for (int j = 0; j < 4; j++)
#pragma unroll
            for (int e = 0; e < 4; e++) C[i][j][e] = 0.f;

    float4 a0r, a1r, b0r, b1r;
    a0r = *(const float4*)(Ag);
    a1r = *(const float4*)(Ag + 4);
    b0r = *(const float4*)(Bg + (size_t)bkr * Edim);
    b1r = *(const float4*)(Bg + (size_t)bkr * Edim + 4);
    {
        float av[8] = {a0r.x, a0r.y, a0r.z, a0r.w, a1r.x, a1r.y, a1r.z, a1r.w};
        float bw[8] = {b0r.x, b0r.y, b0r.z, b0r.w, b1r.x, b1r.y, b1r.z, b1r.w};
        unsigned short ah[8], al[8], bh[8], bl[8];
#pragma unroll
        for (int j = 0; j < 8; j++) { cvt_hilo(av[j], ah[j], al[j]); cvt_hilo(bw[j], bh[j], bl[j]); }
        *(uint4*)&As_h[0][arow][apart] = make_uint4(pk(ah[0],ah[1]), pk(ah[2],ah[3]), pk(ah[4],ah[5]), pk(ah[6],ah[7]));
        *(uint4*)&As_l[0][arow][apart] = make_uint4(pk(al[0],al[1]), pk(al[2],al[3]), pk(al[4],al[5]), pk(al[6],al[7]));
        *(uint4*)&Bs_h[0][bkr][bj]     = make_uint4(pk(bh[0],bh[1]), pk(bh[2],bh[3]), pk(bh[4],bh[5]), pk(bh[6],bh[7]));
        *(uint4*)&Bs_l[0][bkr][bj]     = make_uint4(pk(bl[0],bl[1]), pk(bl[2],bl[3]), pk(bl[4],bl[5]), pk(bl[6],bl[7]));
    }
    __syncthreads();

    const int lrow = lane & 15;
    const int lkoff = (lane >> 4) * 8;

    int buf = 0;
    for (int k0 = 0; k0 < Adim; k0 += 16) {
        const bool more = (k0 + 16) < Adim;
        if (more) {
            a0r = *(const float4*)(Ag + k0 + 16);
            a1r = *(const float4*)(Ag + k0 + 20);
            b0r = *(const float4*)(Bg + (size_t)(k0 + 16 + bkr) * Edim);
            b1r = *(const float4*)(Bg + (size_t)(k0 + 16 + bkr) * Edim + 4);
        }

        unsigned a_hi[4][4], a_lo[4][4], b_hi[4][2], b_lo[4][2];
#pragma unroll
        for (int mi = 0; mi < 4; mi++) {
            ldsm_x4(a_hi[mi], &As_h[buf][wm * 64 + mi * 16 + lrow][lkoff]);
            ldsm_x4(a_lo[mi], &As_l[buf][wm * 64 + mi * 16 + lrow][lkoff]);
        }
#pragma unroll
        for (int np = 0; np < 2; np++) {
            unsigned r[4];
            ldsm_x4_t(r, &Bs_h[buf][lrow][wn * 32 + np * 16 + lkoff]);
            b_hi[2*np][0] = r[0]; b_hi[2*np][1] = r[1];
            b_hi[2*np+1][0] = r[2]; b_hi[2*np+1][1] = r[3];
            ldsm_x4_t(r, &Bs_l[buf][lrow][wn * 32 + np * 16 + lkoff]);
            b_lo[2*np][0] = r[0]; b_lo[2*np][1] = r[1];
            b_lo[2*np+1][0] = r[2]; b_lo[2*np+1][1] = r[3];
        }
#pragma unroll
        for (int mi = 0; mi < 4; mi++)
#pragma unroll
            for (int ni = 0; ni < 4; ni++) {
                mma_bf16(C[mi][ni], a_hi[mi], b_hi[ni]);
                mma_bf16(C[mi][ni], a_hi[mi], b_lo[ni]);
                mma_bf16(C[mi][ni], a_lo[mi], b_hi[ni]);
            }

        if (more) {
            int nb = buf ^ 1;
            float av[8] = {a0r.x, a0r.y, a0r.z, a0r.w, a1r.x, a1r.y, a1r.z, a1r.w};
            float bw[8] = {b0r.x, b0r.y, b0r.z, b0r.w, b1r.x, b1r.y, b1r.z, b1r.w};
            unsigned short ah[8], al[8], bh[8], bl[8];
#pragma unroll
            for (int j = 0; j < 8; j++) { cvt_hilo(av[j], ah[j], al[j]); cvt_hilo(bw[j], bh[j], bl[j]); }
            *(uint4*)&As_h[nb][arow][apart] = make_uint4(pk(ah[0],ah[1]), pk(ah[2],ah[3]), pk(ah[4],ah[5]), pk(ah[6],ah[7]));
            *(uint4*)&As_l[nb][arow][apart] = make_uint4(pk(al[0],al[1]), pk(al[2],al[3]), pk(al[4],al[5]), pk(al[6],al[7]));
            *(uint4*)&Bs_h[nb][bkr][bj]     = make_uint4(pk(bh[0],bh[1]), pk(bh[2],bh[3]), pk(bh[4],bh[5]), pk(bh[6],bh[7]));
            *(uint4*)&Bs_l[nb][bkr][bj]     = make_uint4(pk(bl[0],bl[1]), pk(bl[2],bl[3]), pk(bl[4],bl[5]), pk(bl[6],bl[7]));
        }
        __syncthreads();
        buf ^= 1;
    }

#pragma unroll
    for (int mi = 0; mi < 4; mi++)
#pragma unroll
        for (int ni = 0; ni < 4; ni++) {
            int gm = m0 + wm * 64 + mi * 16 + (lane >> 2);
            int gc = n0 + wn * 32 + ni * 8 + (lane & 3) * 2;
            float b0f = bo[gc], b1f = bo[gc + 1];
            float* p0 = out + (size_t)gm * Edim + gc;
            *(float2*)p0 = make_float2(C[mi][ni][0] + b0f, C[mi][ni][1] + b1f);
            float* p1 = out + (size_t)(gm + 8) * Edim + gc;
            *(float2*)p1 = make_float2(C[mi][ni][2] + b0f, C[mi][ni][3] + b1f);
        }
}

extern "C" void kernel_launch(void* const* d_in, const int* in_sizes, int n_in,
                              void* d_out, int out_size)
{
    const float* x  = (const float*)d_in[0];
    const float* Wq = (const float*)d_in[1];
    const float* bq = (const float*)d_in[2];
    const float* Wk = (const float*)d_in[3];
    const float* bk = (const float*)d_in[4];
    const float* Wv = (const float*)d_in[5];
    const float* bv = (const float*)d_in[6];
    const float* Wo = (const float*)d_in[7];
    const float* bo = (const float*)d_in[8];
    float* out = (float*)d_out;

    dim3 g1(Mrows / 128, (3 * Hn * DHd) / 128);   // (32, 24)
    qkv_kernel<<<g1, 256>>>(x, Wq, bq, Wk, bk, Wv, bv);

    dim3 g2(Sdim / 128, Bsz * Hn);                // (16, 32)
    attn_kernel<<<g2, 256>>>();

    dim3 g3(Mrows / 128, Edim / 128);             // (32, 8)
    outproj_kernel<<<g3, 256>>>(Wo, bo, out);
}